// round 13
// baseline (speedup 1.0000x reference)
#include <cuda_runtime.h>
#include <cuda_bf16.h>
#include <math.h>
#include <stdint.h>

// ---------------------------------------------------------------------------
// Problem constants
// ---------------------------------------------------------------------------
#define BATCH 8
#define CIN   256
#define EMB   512
#define HW    48
#define NPIX  2304
#define KDIM  2304

// ---------------------------------------------------------------------------
// Scratch (packed split u32: (bf16hi<<16)|bf16lo). ~260 MB.
//   COL aliased -> fp32 att -> packed att (softmax in place)
// ---------------------------------------------------------------------------
#define COL_BYTES ((size_t)BATCH * NPIX * KDIM * 4)
#define W_BYTES   ((size_t)EMB * KDIM * 4)
#define QT_BYTES  ((size_t)BATCH * NPIX * EMB * 4)

#define OFF_COL  ((size_t)0)
#define OFF_WQ   (OFF_COL + COL_BYTES)
#define OFF_WK   (OFF_WQ + W_BYTES)
#define OFF_WV   (OFF_WK + W_BYTES)
#define OFF_QT   (OFF_WV + W_BYTES)
#define OFF_KT   (OFF_QT + QT_BYTES)
#define OFF_VP   (OFF_KT + QT_BYTES)
#define SCRATCH_BYTES (OFF_VP + QT_BYTES)

__device__ __align__(1024) unsigned char g_scratch[SCRATCH_BYTES];

// ---------------------------------------------------------------------------
// Helpers
// ---------------------------------------------------------------------------
__device__ __forceinline__ uint32_t smem_u32(const void* p) {
    uint32_t a;
    asm("{ .reg .u64 t; cvta.to.shared.u64 t, %1; cvt.u32.u64 %0, t; }"
        : "=r"(a) : "l"(p));
    return a;
}

// SW64 swizzle: 16B column bits [4:6) ^= offset bits [7:9)
#define SWZ64(o) ((o) ^ (((o) >> 3) & 0x30))

__device__ __forceinline__ uint32_t pack_split(float x) {
    __nv_bfloat16 h = __float2bfloat16(x);
    float hf = __bfloat162float(h);
    __nv_bfloat16 l = __float2bfloat16(x - hf);
    return ((uint32_t)__bfloat16_as_ushort(h) << 16) | (uint32_t)__bfloat16_as_ushort(l);
}
__device__ __forceinline__ float unpack_split(uint32_t p) {
    float hi = __bfloat162float(__ushort_as_bfloat16((unsigned short)(p >> 16)));
    float lo = __bfloat162float(__ushort_as_bfloat16((unsigned short)(p & 0xFFFF)));
    return hi + lo;
}

__device__ __forceinline__ void ldsm4(uint32_t& r0, uint32_t& r1, uint32_t& r2,
                                      uint32_t& r3, uint32_t addr) {
    asm volatile("ldmatrix.sync.aligned.m8n8.x4.shared.b16 {%0,%1,%2,%3}, [%4];"
                 : "=r"(r0), "=r"(r1), "=r"(r2), "=r"(r3) : "r"(addr));
}
__device__ __forceinline__ void mma16816(float* d, const uint32_t* a,
                                         const uint32_t* b) {
    asm volatile(
        "mma.sync.aligned.m16n8k16.row.col.f32.bf16.bf16.f32 "
        "{%0,%1,%2,%3},{%4,%5,%6,%7},{%8,%9},{%0,%1,%2,%3};"
        : "+f"(d[0]), "+f"(d[1]), "+f"(d[2]), "+f"(d[3])
        : "r"(a[0]), "r"(a[1]), "r"(a[2]), "r"(a[3]), "r"(b[0]), "r"(b[1]));
}
__device__ __forceinline__ void sts64b(uint32_t addr, uint32_t lo, uint32_t hi) {
    unsigned long long v = ((unsigned long long)hi << 32) | lo;
    asm volatile("st.shared.b64 [%0], %1;" :: "r"(addr), "l"(v) : "memory");
}

// ---------------------------------------------------------------------------
// Converters (packed u32)
// ---------------------------------------------------------------------------
__global__ void pack_weights(const float* __restrict__ Wq, const float* __restrict__ Wk,
                             const float* __restrict__ Wv,
                             uint32_t* __restrict__ oq, uint32_t* __restrict__ ok,
                             uint32_t* __restrict__ ov)
{
    long i = (long)blockIdx.x * 256 + threadIdx.x;
    const long n = (long)EMB * KDIM;
    if (i >= n) return;
    oq[i] = pack_split(Wq[i]);
    ok[i] = pack_split(Wk[i]);
    ov[i] = pack_split(Wv[i]);
}

// colT[b][n][k] packed; vectorized: each thread does 4 consecutive k.
__global__ void build_colT(const float* __restrict__ feat, uint32_t* __restrict__ colT)
{
    long idx = (long)blockIdx.x * 256 + threadIdx.x;          // quad index
    const long total = (long)BATCH * NPIX * (KDIM / 4);
    if (idx >= total) return;
    int kq = (int)(idx % (KDIM / 4));
    long t = idx / (KDIM / 4);
    int n = (int)(t % NPIX);
    int b = (int)(t / NPIX);
    int h = n / HW, w = n - HW * h;
    const float* fb = feat + (long)b * CIN * HW * HW;
    uint4 o;
    uint32_t* op = &o.x;
#pragma unroll
    for (int q = 0; q < 4; q++) {
        int k = kq * 4 + q;
        int c = k / 9, k9 = k - 9 * c;
        int ky = k9 / 3, kx = k9 - 3 * ky;
        int hs = h + ky - 1, ws = w + kx - 1;
        float v = 0.f;
        if (hs >= 0 && hs < HW && ws >= 0 && ws < HW)
            v = fb[((long)c * HW + hs) * HW + ws];
        op[q] = pack_split(v);
    }
    *(uint4*)(colT + ((long)(b * NPIX + n) * KDIM + kq * 4)) = o;
}

// ---------------------------------------------------------------------------
// GEMM: D[m][n] = sum_k A[m][k]*B[n][k], split-bf16 3-MMA, fp32 acc.
// All operands packed-split u32. LDG(uint4)->PRMT split->STS.
// 128x128 CTA, 8 warps (2x4), warp 64x32, KC=32.
// DUAL-CTA design: __launch_bounds__(256,2) (<=128 regs, 2 CTAs/SM).
// SINGLE 32KB smem stage, two syncs per chunk:
//   STS(c) -> sync -> compute(c) -> LDG(c+1) -> sync
// Load/sync bubbles of one CTA are covered by the co-resident CTA's MMAs.
// MODE: 0 fp32 out | 1 q/k conv (bias[col], packed out, z&1 selects) |
//       2 v conv (bias[row], packed out) |
//       3 output GEMM: fused transpose + residual -> Cf[b][n][m] += unpack(Cp)
// Stage: [Ah 8K][Al 8K][Bh 8K][Bl 8K] = 32KB.
// ---------------------------------------------------------------------------
#define SM_MAIN 32768
#define TPAD 132     // fp32 transpose tile row stride (words)
#define SM_OUT  (128 * TPAD * 4)   // 67584 (MODE 3: transpose buffer)

template<int MODE>
__global__ __launch_bounds__(256, 2)
void gemm_mma(const uint32_t* __restrict__ A, long sA, int lda,
              const uint32_t* __restrict__ B, long sB, int ldb,
              const uint32_t* __restrict__ Balt,
              int K,
              float* __restrict__ Cf, long sCf, int ldc,
              uint32_t* __restrict__ Cp, uint32_t* __restrict__ Cp2,
              long sCp, int ldcp,
              const float* __restrict__ bias0, const float* __restrict__ bias1)
{
    extern __shared__ __align__(128) unsigned char smem[];
    const uint32_t sbase = smem_u32(smem);
    const int tid = threadIdx.x, lid = tid & 31, wid = tid >> 5;
    const int warp_m = wid >> 2, warp_n = wid & 3;

    int bz = blockIdx.z, b, wsel = 0;
    if (MODE == 1) { b = bz >> 1; wsel = bz & 1; } else { b = bz; }
    const int bm = blockIdx.y * 128, bn = blockIdx.x * 128;

    const uint32_t* Ab = A + (long)b * sA;
    const uint32_t* Bb = (MODE == 1) ? (wsel ? Balt : B) : (B + (long)b * sB);

    // ---- loader mappings: uint4 segments (8 per 32-u32 row) ----
    const uint32_t* apg[4]; uint32_t ash[4];
    const uint32_t* bpg[4]; uint32_t bsh[4];
#pragma unroll
    for (int i = 0; i < 4; i++) {
        int f = tid + 256 * i; int r = f >> 3; int seg = f & 7;
        apg[i] = Ab + (long)(bm + r) * lda + seg * 4;
        bpg[i] = Bb + (long)(bn + r) * ldb + seg * 4;
        ash[i] = SWZ64((uint32_t)(r * 64 + seg * 8));
        bsh[i] = ash[i];
    }

    uint4 rga[4], rgb[4];
    auto ldg_all = [&](int c) {
#pragma unroll
        for (int i = 0; i < 4; i++) rga[i] = *(const uint4*)(apg[i] + (long)c * 32);
#pragma unroll
        for (int i = 0; i < 4; i++) rgb[i] = *(const uint4*)(bpg[i] + (long)c * 32);
    };
    auto sts_all = [&]() {
        const uint32_t ab = sbase;
        const uint32_t bb = sbase + 16384u;
#pragma unroll
        for (int i = 0; i < 4; i++) {
            sts64b(ab + ash[i],
                   __byte_perm(rga[i].x, rga[i].y, 0x7632),
                   __byte_perm(rga[i].z, rga[i].w, 0x7632));
            sts64b(ab + 8192u + ash[i],
                   __byte_perm(rga[i].x, rga[i].y, 0x5410),
                   __byte_perm(rga[i].z, rga[i].w, 0x5410));
        }
#pragma unroll
        for (int i = 0; i < 4; i++) {
            sts64b(bb + bsh[i],
                   __byte_perm(rgb[i].x, rgb[i].y, 0x7632),
                   __byte_perm(rgb[i].z, rgb[i].w, 0x7632));
            sts64b(bb + 8192u + bsh[i],
                   __byte_perm(rgb[i].x, rgb[i].y, 0x5410),
                   __byte_perm(rgb[i].z, rgb[i].w, 0x5410));
        }
    };

    float acc[4][4][4];
#pragma unroll
    for (int i = 0; i < 4; i++)
#pragma unroll
        for (int j = 0; j < 4; j++)
#pragma unroll
            for (int r = 0; r < 4; r++) acc[i][j][r] = 0.f;

    const int sub = lid >> 3, l7 = lid & 7;
    const int arow0 = warp_m * 64 + (sub & 1) * 8 + l7;
    const int brow  = warp_n * 32 + (sub >> 1) * 8 + l7;

    auto compute = [&]() {
        const uint32_t stA  = sbase;
        const uint32_t stBh = sbase + 16384u, stBl = sbase + 24576u;
#pragma unroll
        for (int ks = 0; ks < 2; ks++) {
            uint32_t bh[4][2], bl[4][2];
            const int bkb = ks * 16 + (sub & 1) * 8;
#pragma unroll
            for (int g2 = 0; g2 < 2; g2++) {
                const uint32_t off = SWZ64((uint32_t)((brow + g2 * 16) * 64 + bkb * 2));
                ldsm4(bh[2 * g2][0], bh[2 * g2][1], bh[2 * g2 + 1][0],
                      bh[2 * g2 + 1][1], stBh + off);
                ldsm4(bl[2 * g2][0], bl[2 * g2][1], bl[2 * g2 + 1][0],
                      bl[2 * g2 + 1][1], stBl + off);
            }
            const int akb = ks * 16 + (sub >> 1) * 8;
#pragma unroll
            for (int i = 0; i < 4; i++) {
                uint32_t ah[4], al[4];
                const uint32_t off = SWZ64((uint32_t)((arow0 + i * 16) * 64 + akb * 2));
                ldsm4(ah[0], ah[1], ah[2], ah[3], stA + off);
                ldsm4(al[0], al[1], al[2], al[3], stA + 8192u + off);
#pragma unroll
                for (int j = 0; j < 4; j++) {
                    mma16816(acc[i][j], ah, bh[j]);
                    mma16816(acc[i][j], ah, bl[j]);
                    mma16816(acc[i][j], al, bh[j]);
                }
            }
        }
    };

    const int nchunk = K / 32;

    // dual-CTA simple pipeline: one stage, two syncs per chunk
    ldg_all(0);
    for (int c = 0; c < nchunk; c++) {
        sts_all();
        __syncthreads();
        compute();
        if (c + 1 < nchunk) ldg_all(c + 1);
        __syncthreads();
    }

    // ---- epilogue ----
    if (MODE == 3) {
        // transpose via smem, then out[b][e][n_pix] = acc^T + unpack(vP)
        float* T = (float*)smem;
#pragma unroll
        for (int i = 0; i < 4; i++)
#pragma unroll
            for (int j = 0; j < 4; j++) {
                const int ml = warp_m * 64 + i * 16 + (lid >> 2);
                const int nl = warp_n * 32 + j * 8 + (lid & 3) * 2;
                T[nl * TPAD + ml]           = acc[i][j][0];
                T[(nl + 1) * TPAD + ml]     = acc[i][j][1];
                T[nl * TPAD + ml + 8]       = acc[i][j][2];
                T[(nl + 1) * TPAD + ml + 8] = acc[i][j][3];
            }
        __syncthreads();
        float*          ob = Cf + (long)b * sCf;     // out  [E][NPIX]
        const uint32_t* vb = Cp + (long)b * sCp;     // vP   [E][NPIX]
        for (int it = tid; it < 128 * 32; it += 256) {
            const int row = it >> 5;        // emb within tile
            const int c4  = (it & 31) * 4;  // pixel within tile
            float4 tv = *(const float4*)&T[row * TPAD + c4];
            const long off = (long)(bn + row) * ldc + bm + c4;
            uint4 vp = *(const uint4*)(vb + off);
            float4 o;
            o.x = tv.x + unpack_split(vp.x);
            o.y = tv.y + unpack_split(vp.y);
            o.z = tv.z + unpack_split(vp.z);
            o.w = tv.w + unpack_split(vp.w);
            *(float4*)(ob + off) = o;
        }
        return;
    }

    const float* bias = (MODE == 1) ? (wsel ? bias1 : bias0) : bias0;
#pragma unroll
    for (int i = 0; i < 4; i++)
#pragma unroll
        for (int j = 0; j < 4; j++) {
            const int m = bm + warp_m * 64 + i * 16 + (lid >> 2);
            const int n = bn + warp_n * 32 + j * 8 + (lid & 3) * 2;
            const float d0 = acc[i][j][0], d1 = acc[i][j][1];
            const float d2 = acc[i][j][2], d3 = acc[i][j][3];
            if (MODE == 0) {
                float* bp = Cf + (long)b * sCf;
                *(float2*)(bp + (long)m * ldc + n)       = make_float2(d0, d1);
                *(float2*)(bp + (long)(m + 8) * ldc + n) = make_float2(d2, d3);
            } else if (MODE == 1) {
                uint32_t* dst = (wsel ? Cp2 : Cp) + (long)b * sCp;
                const float b0 = bias[n], b1 = bias[n + 1];
                *(uint2*)(dst + (long)m * ldcp + n) =
                    make_uint2(pack_split(d0 + b0), pack_split(d1 + b1));
                *(uint2*)(dst + (long)(m + 8) * ldcp + n) =
                    make_uint2(pack_split(d2 + b0), pack_split(d3 + b1));
            } else {
                uint32_t* bp = Cp + (long)b * sCp;
                const float bm0 = bias[m], bm8 = bias[m + 8];
                *(uint2*)(bp + (long)m * ldcp + n) =
                    make_uint2(pack_split(d0 + bm0), pack_split(d1 + bm0));
                *(uint2*)(bp + (long)(m + 8) * ldcp + n) =
                    make_uint2(pack_split(d2 + bm8), pack_split(d3 + bm8));
            }
        }
}

// ---------------------------------------------------------------------------
// Softmax over rows of att (fp32 in), writes packed split u32 IN PLACE.
// 192 threads, float4 vectorized: 576 float4 per row = 3 per thread.
// ---------------------------------------------------------------------------
__global__ __launch_bounds__(192)
void softmax_pack(float* __restrict__ att)
{
    const long row = blockIdx.x;
    float4* p4 = (float4*)(att + row * NPIX);
    uint4*  u4 = (uint4*)(att + row * NPIX);
    __shared__ float red[192];
    const int t = threadIdx.x;

    float4 v[3];
    float m = -INFINITY;
#pragma unroll
    for (int i = 0; i < 3; i++) {
        v[i] = p4[t + i * 192];
        m = fmaxf(m, fmaxf(fmaxf(v[i].x, v[i].y), fmaxf(v[i].z, v[i].w)));
    }
    red[t] = m; __syncthreads();
    if (t < 64) red[t] = fmaxf(red[t], fmaxf(red[t + 64], red[t + 128]));
    __syncthreads();
    for (int s = 32; s > 0; s >>= 1) {
        if (t < s) red[t] = fmaxf(red[t], red[t + s]);
        __syncthreads();
    }
    m = red[0]; __syncthreads();

    float sum = 0.f;
#pragma unroll
    for (int i = 0; i < 3; i++) {
        v[i].x = __expf(v[i].x - m); v[i].y = __expf(v[i].y - m);
        v[i].z = __expf(v[i].z - m); v[i].w = __expf(v[i].w - m);
        sum += (v[i].x + v[i].y) + (v[i].z + v[i].w);
    }
    red[t] = sum; __syncthreads();
    if (t < 64) red[t] = red[t] + red[t + 64] + red[t + 128];
    __syncthreads();
    for (int s = 32; s > 0; s >>= 1) {
        if (t < s) red[t] += red[t + s];
        __syncthreads();
    }
    const float inv = 1.f / red[0];
#pragma unroll
    for (int i = 0; i < 3; i++) {
        uint4 o;
        o.x = pack_split(v[i].x * inv);
        o.y = pack_split(v[i].y * inv);
        o.z = pack_split(v[i].z * inv);
        o.w = pack_split(v[i].w * inv);
        u4[t + i * 192] = o;
    }
}

// ---------------------------------------------------------------------------
// launch
// ---------------------------------------------------------------------------
extern "C" void kernel_launch(void* const* d_in, const int* in_sizes, int n_in,
                              void* d_out, int out_size)
{
    const float* feat = (const float*)d_in[0];
    const float* Wq   = (const float*)d_in[1];
    const float* bq   = (const float*)d_in[2];
    const float* Wk   = (const float*)d_in[3];
    const float* bk   = (const float*)d_in[4];
    const float* Wv   = (const float*)d_in[5];
    const float* bv   = (const float*)d_in[6];
    float* out = (float*)d_out;

    unsigned char* base;
    cudaGetSymbolAddress((void**)&base, g_scratch);
    uint32_t* colT = (uint32_t*)(base + OFF_COL);
    uint32_t* wqP  = (uint32_t*)(base + OFF_WQ);
    uint32_t* wkP  = (uint32_t*)(base + OFF_WK);
    uint32_t* wvP  = (uint32_t*)(base + OFF_WV);
    uint32_t* qT   = (uint32_t*)(base + OFF_QT);
    uint32_t* kT   = (uint32_t*)(base + OFF_KT);
    uint32_t* vP   = (uint32_t*)(base + OFF_VP);
    float*    att  = (float*)   (base + OFF_COL);   // alias; colT dead by then

    auto kQK  = gemm_mma<1>;
    auto kV   = gemm_mma<2>;
    auto kLOG = gemm_mma<0>;
    auto kOUT = gemm_mma<3>;
    cudaFuncSetAttribute(kQK,  cudaFuncAttributeMaxDynamicSharedMemorySize, SM_MAIN);
    cudaFuncSetAttribute(kV,   cudaFuncAttributeMaxDynamicSharedMemorySize, SM_MAIN);
    cudaFuncSetAttribute(kLOG, cudaFuncAttributeMaxDynamicSharedMemorySize, SM_MAIN);
    cudaFuncSetAttribute(kOUT, cudaFuncAttributeMaxDynamicSharedMemorySize, SM_OUT);

    // 1) pack weights + build packed im2col
    {
        long n = (long)EMB * KDIM;
        pack_weights<<<(unsigned)((n + 255) / 256), 256>>>(Wq, Wk, Wv, wqP, wkP, wvP);
        long total = (long)BATCH * NPIX * (KDIM / 4);
        build_colT<<<(unsigned)((total + 255) / 256), 256>>>(feat, colT);
    }

    const long colS = (long)NPIX * KDIM;
    const long qtS  = (long)NPIX * EMB;
    const long attS = (long)NPIX * NPIX;

    // 2) q,k conv: D[n][e] = colT[n][:] . W[e][:] + bias[e]  (packed out)
    {
        dim3 grid(EMB / 128, NPIX / 128, 2 * BATCH);
        kQK<<<grid, 256, SM_MAIN>>>(colT, colS, KDIM,
                                    wqP, 0, KDIM, wkP, KDIM,
                                    nullptr, 0, 0,
                                    qT, kT, qtS, EMB,
                                    bq, bk);
    }
    // 3) v conv: D[e][n] = Wv[e][:] . colT[n][:] + bias[e]  (packed out)
    {
        dim3 grid(NPIX / 128, EMB / 128, BATCH);
        kV<<<grid, 256, SM_MAIN>>>(wvP, 0, KDIM,
                                   colT, colS, KDIM, nullptr, KDIM,
                                   nullptr, 0, 0,
                                   vP, nullptr, qtS, NPIX,
                                   bv, nullptr);
    }
    // 4) logits: att[i][j] = qT[i][:] . kT[j][:]  (K=512, fp32 out)
    {
        dim3 grid(NPIX / 128, NPIX / 128, BATCH);
        kLOG<<<grid, 256, SM_MAIN>>>(qT, qtS, EMB,
                                     kT, qtS, EMB, nullptr, EMB,
                                     att, attS, NPIX,
                                     nullptr, nullptr, 0, 0,
                                     nullptr, nullptr);
    }
    // 5) softmax rows + pack u32 in place (vectorized)
    softmax_pack<<<BATCH * NPIX, 192>>>(att);

    // 6) output GEMM + fused transpose/residual:
    //    out[b][e][n] = (att[n][:] . vP[e][:]) + unpack(vP[b][e][n])
    {
        dim3 grid(EMB / 128, NPIX / 128, BATCH);
        kOUT<<<grid, 256, SM_OUT>>>((const uint32_t*)att, attS, NPIX,
                                    vP, qtS, NPIX, nullptr, NPIX,
                                    out, (long)EMB * NPIX, NPIX,
                                    vP, nullptr, qtS, NPIX,
                                    nullptr, nullptr);
    }
}

// round 14
// speedup vs baseline: 1.2396x; 1.2396x over previous
#include <cuda_runtime.h>
#include <cuda_bf16.h>
#include <math.h>
#include <stdint.h>

// ---------------------------------------------------------------------------
// Problem constants
// ---------------------------------------------------------------------------
#define BATCH 8
#define CIN   256
#define EMB   512
#define HW    48
#define NPIX  2304
#define KDIM  2304

// ---------------------------------------------------------------------------
// Scratch (packed split u32: (bf16hi<<16)|bf16lo). ~260 MB.
//   COL aliased -> fp32 att -> packed att (softmax in place)
// ---------------------------------------------------------------------------
#define COL_BYTES ((size_t)BATCH * NPIX * KDIM * 4)
#define W_BYTES   ((size_t)EMB * KDIM * 4)
#define QT_BYTES  ((size_t)BATCH * NPIX * EMB * 4)

#define OFF_COL  ((size_t)0)
#define OFF_WQ   (OFF_COL + COL_BYTES)
#define OFF_WK   (OFF_WQ + W_BYTES)
#define OFF_WV   (OFF_WK + W_BYTES)
#define OFF_QT   (OFF_WV + W_BYTES)
#define OFF_KT   (OFF_QT + QT_BYTES)
#define OFF_VP   (OFF_KT + QT_BYTES)
#define SCRATCH_BYTES (OFF_VP + QT_BYTES)

__device__ __align__(1024) unsigned char g_scratch[SCRATCH_BYTES];

// ---------------------------------------------------------------------------
// Helpers
// ---------------------------------------------------------------------------
__device__ __forceinline__ uint32_t smem_u32(const void* p) {
    uint32_t a;
    asm("{ .reg .u64 t; cvta.to.shared.u64 t, %1; cvt.u32.u64 %0, t; }"
        : "=r"(a) : "l"(p));
    return a;
}

// SW64 swizzle: 16B column bits [4:6) ^= offset bits [7:9)
#define SWZ64(o) ((o) ^ (((o) >> 3) & 0x30))

__device__ __forceinline__ uint32_t pack_split(float x) {
    __nv_bfloat16 h = __float2bfloat16(x);
    float hf = __bfloat162float(h);
    __nv_bfloat16 l = __float2bfloat16(x - hf);
    return ((uint32_t)__bfloat16_as_ushort(h) << 16) | (uint32_t)__bfloat16_as_ushort(l);
}
__device__ __forceinline__ float unpack_split(uint32_t p) {
    float hi = __bfloat162float(__ushort_as_bfloat16((unsigned short)(p >> 16)));
    float lo = __bfloat162float(__ushort_as_bfloat16((unsigned short)(p & 0xFFFF)));
    return hi + lo;
}

__device__ __forceinline__ void ldsm4(uint32_t& r0, uint32_t& r1, uint32_t& r2,
                                      uint32_t& r3, uint32_t addr) {
    asm volatile("ldmatrix.sync.aligned.m8n8.x4.shared.b16 {%0,%1,%2,%3}, [%4];"
                 : "=r"(r0), "=r"(r1), "=r"(r2), "=r"(r3) : "r"(addr));
}
__device__ __forceinline__ void mma16816(float* d, const uint32_t* a,
                                         const uint32_t* b) {
    asm volatile(
        "mma.sync.aligned.m16n8k16.row.col.f32.bf16.bf16.f32 "
        "{%0,%1,%2,%3},{%4,%5,%6,%7},{%8,%9},{%0,%1,%2,%3};"
        : "+f"(d[0]), "+f"(d[1]), "+f"(d[2]), "+f"(d[3])
        : "r"(a[0]), "r"(a[1]), "r"(a[2]), "r"(a[3]), "r"(b[0]), "r"(b[1]));
}
__device__ __forceinline__ void sts64b(uint32_t addr, uint32_t lo, uint32_t hi) {
    unsigned long long v = ((unsigned long long)hi << 32) | lo;
    asm volatile("st.shared.b64 [%0], %1;" :: "r"(addr), "l"(v) : "memory");
}
__device__ __forceinline__ void bar_sync(int id, int cnt) {
    asm volatile("bar.sync %0, %1;" :: "r"(id), "r"(cnt) : "memory");
}
__device__ __forceinline__ void bar_arrive(int id, int cnt) {
    asm volatile("bar.arrive %0, %1;" :: "r"(id), "r"(cnt) : "memory");
}

// ---------------------------------------------------------------------------
// Converters (packed u32)
// ---------------------------------------------------------------------------
__global__ void pack_weights(const float* __restrict__ Wq, const float* __restrict__ Wk,
                             const float* __restrict__ Wv,
                             uint32_t* __restrict__ oq, uint32_t* __restrict__ ok,
                             uint32_t* __restrict__ ov)
{
    long i = (long)blockIdx.x * 256 + threadIdx.x;
    const long n = (long)EMB * KDIM;
    if (i >= n) return;
    oq[i] = pack_split(Wq[i]);
    ok[i] = pack_split(Wk[i]);
    ov[i] = pack_split(Wv[i]);
}

// colT[b][n][k] packed; vectorized: each thread does 4 consecutive k.
__global__ void build_colT(const float* __restrict__ feat, uint32_t* __restrict__ colT)
{
    long idx = (long)blockIdx.x * 256 + threadIdx.x;          // quad index
    const long total = (long)BATCH * NPIX * (KDIM / 4);
    if (idx >= total) return;
    int kq = (int)(idx % (KDIM / 4));
    long t = idx / (KDIM / 4);
    int n = (int)(t % NPIX);
    int b = (int)(t / NPIX);
    int h = n / HW, w = n - HW * h;
    const float* fb = feat + (long)b * CIN * HW * HW;
    uint4 o;
    uint32_t* op = &o.x;
#pragma unroll
    for (int q = 0; q < 4; q++) {
        int k = kq * 4 + q;
        int c = k / 9, k9 = k - 9 * c;
        int ky = k9 / 3, kx = k9 - 3 * ky;
        int hs = h + ky - 1, ws = w + kx - 1;
        float v = 0.f;
        if (hs >= 0 && hs < HW && ws >= 0 && ws < HW)
            v = fb[((long)c * HW + hs) * HW + ws];
        op[q] = pack_split(v);
    }
    *(uint4*)(colT + ((long)(b * NPIX + n) * KDIM + kq * 4)) = o;
}

// ---------------------------------------------------------------------------
// Warp-specialized GEMM: D[m][n] = sum_k A[m][k]*B[n][k], split-bf16 3-MMA.
// 384 threads = 8 compute warps (2x4, warp 64x32, 128x128 CTA tile)
//             + 4 loader warps (LDG packed u32 -> PRMT split -> STS).
// 4 smem stages x 32KB; producer/consumer named barriers:
//   full[s]=1+s (loader arrives, compute syncs), empty[s]=5+s (reverse).
// Loader runs up to 4 chunks ahead; compute path has no LDG/STS at all.
// MODE: 0 fp32 out | 1 q/k conv (bias[col], packed out, z&1 selects) |
//       2 v conv (bias[row], packed out) |
//       3 output GEMM: fused transpose + residual
// Stage: [Ah 8K][Al 8K][Bh 8K][Bl 8K] = 32KB; total 128KB.
// ---------------------------------------------------------------------------
#define SMEM_TOTAL 131072
#define TPAD 132     // fp32 transpose tile row stride (words)

template<int MODE>
__global__ __launch_bounds__(384, 1)
void gemm_mma(const uint32_t* __restrict__ A, long sA, int lda,
              const uint32_t* __restrict__ B, long sB, int ldb,
              const uint32_t* __restrict__ Balt,
              int K,
              float* __restrict__ Cf, long sCf, int ldc,
              uint32_t* __restrict__ Cp, uint32_t* __restrict__ Cp2,
              long sCp, int ldcp,
              const float* __restrict__ bias0, const float* __restrict__ bias1)
{
    extern __shared__ __align__(128) unsigned char smem[];
    const uint32_t sbase = smem_u32(smem);
    const int tid = threadIdx.x, lid = tid & 31, wid = tid >> 5;

    int bz = blockIdx.z, b, wsel = 0;
    if (MODE == 1) { b = bz >> 1; wsel = bz & 1; } else { b = bz; }
    const int bm = blockIdx.y * 128, bn = blockIdx.x * 128;

    const uint32_t* Ab = A + (long)b * sA;
    const uint32_t* Bb = (MODE == 1) ? (wsel ? Balt : B) : (B + (long)b * sB);

    const int nchunk = K / 32;

    float acc[4][4][4];
#pragma unroll
    for (int i = 0; i < 4; i++)
#pragma unroll
        for (int j = 0; j < 4; j++)
#pragma unroll
            for (int r = 0; r < 4; r++) acc[i][j][r] = 0.f;

    const int warp_m = wid >> 2, warp_n = wid & 3;   // meaningful for wid<8
    const int sub = lid >> 3, l7 = lid & 7;
    const int arow0 = warp_m * 64 + (sub & 1) * 8 + l7;
    const int brow  = warp_n * 32 + (sub >> 1) * 8 + l7;

    if (wid >= 8) {
        // ================= loader warps (128 threads) =================
        const int ltid = tid - 256;
        const int r0 = ltid >> 3, s0 = ltid & 7;       // (row base, segment)
        const uint32_t* pA = Ab + (long)(bm + r0) * lda + s0 * 4;
        const uint32_t* pB = Bb + (long)(bn + r0) * ldb + s0 * 4;
        const uint32_t oFF = SWZ64((uint32_t)(r0 * 64 + s0 * 8));
        uint4 ra[8], rb[8];
        for (int c = 0; c < nchunk; c++) {
            const int s = c & 3;
#pragma unroll
            for (int i = 0; i < 8; i++)
                ra[i] = *(const uint4*)(pA + (long)(i * 16) * lda + (long)c * 32);
#pragma unroll
            for (int i = 0; i < 8; i++)
                rb[i] = *(const uint4*)(pB + (long)(i * 16) * ldb + (long)c * 32);
            if (c >= 4) bar_sync(5 + s, 384);          // wait stage free
            const uint32_t ab  = sbase + (uint32_t)s * 32768u;
            const uint32_t bbs = ab + 16384u;
#pragma unroll
            for (int i = 0; i < 8; i++) {
                const uint32_t o = oFF + 1024u * i;
                sts64b(ab + o,
                       __byte_perm(ra[i].x, ra[i].y, 0x7632),
                       __byte_perm(ra[i].z, ra[i].w, 0x7632));
                sts64b(ab + 8192u + o,
                       __byte_perm(ra[i].x, ra[i].y, 0x5410),
                       __byte_perm(ra[i].z, ra[i].w, 0x5410));
            }
#pragma unroll
            for (int i = 0; i < 8; i++) {
                const uint32_t o = oFF + 1024u * i;
                sts64b(bbs + o,
                       __byte_perm(rb[i].x, rb[i].y, 0x7632),
                       __byte_perm(rb[i].z, rb[i].w, 0x7632));
                sts64b(bbs + 8192u + o,
                       __byte_perm(rb[i].x, rb[i].y, 0x5410),
                       __byte_perm(rb[i].z, rb[i].w, 0x5410));
            }
            bar_arrive(1 + s, 384);                    // stage full
        }
    } else {
        // ================= compute warps (256 threads) =================
        for (int c = 0; c < nchunk; c++) {
            const int s = c & 3;
            bar_sync(1 + s, 384);                      // wait stage full
            const uint32_t stA  = sbase + (uint32_t)s * 32768u;
            const uint32_t stBh = stA + 16384u, stBl = stA + 24576u;
#pragma unroll
            for (int ks = 0; ks < 2; ks++) {
                uint32_t bh[4][2], bl[4][2];
                const int bkb = ks * 16 + (sub & 1) * 8;
#pragma unroll
                for (int g2 = 0; g2 < 2; g2++) {
                    const uint32_t off =
                        SWZ64((uint32_t)((brow + g2 * 16) * 64 + bkb * 2));
                    ldsm4(bh[2 * g2][0], bh[2 * g2][1], bh[2 * g2 + 1][0],
                          bh[2 * g2 + 1][1], stBh + off);
                    ldsm4(bl[2 * g2][0], bl[2 * g2][1], bl[2 * g2 + 1][0],
                          bl[2 * g2 + 1][1], stBl + off);
                }
                const int akb = ks * 16 + (sub >> 1) * 8;
#pragma unroll
                for (int i = 0; i < 4; i++) {
                    uint32_t ah[4], al[4];
                    const uint32_t off =
                        SWZ64((uint32_t)((arow0 + i * 16) * 64 + akb * 2));
                    ldsm4(ah[0], ah[1], ah[2], ah[3], stA + off);
                    ldsm4(al[0], al[1], al[2], al[3], stA + 8192u + off);
#pragma unroll
                    for (int j = 0; j < 4; j++) {
                        mma16816(acc[i][j], ah, bh[j]);
                        mma16816(acc[i][j], ah, bl[j]);
                        mma16816(acc[i][j], al, bh[j]);
                    }
                }
            }
            bar_arrive(5 + s, 384);                    // stage free
        }
    }

    // ---- epilogue ----
    if (MODE == 3) {
        // transpose via smem, then out[b][e][n_pix] = acc^T + unpack(vP)
        float* T = (float*)smem;
        if (wid < 8) {
#pragma unroll
            for (int i = 0; i < 4; i++)
#pragma unroll
                for (int j = 0; j < 4; j++) {
                    const int ml = warp_m * 64 + i * 16 + (lid >> 2);
                    const int nl = warp_n * 32 + j * 8 + (lid & 3) * 2;
                    T[nl * TPAD + ml]           = acc[i][j][0];
                    T[(nl + 1) * TPAD + ml]     = acc[i][j][1];
                    T[nl * TPAD + ml + 8]       = acc[i][j][2];
                    T[(nl + 1) * TPAD + ml + 8] = acc[i][j][3];
                }
        }
        __syncthreads();
        float*          ob = Cf + (long)b * sCf;     // out  [E][NPIX]
        const uint32_t* vb = Cp + (long)b * sCp;     // vP   [E][NPIX]
        for (int it = tid; it < 128 * 32; it += 384) {
            const int row = it >> 5;        // emb within tile
            const int c4  = (it & 31) * 4;  // pixel within tile
            float4 tv = *(const float4*)&T[row * TPAD + c4];
            const long off = (long)(bn + row) * ldc + bm + c4;
            uint4 vp = *(const uint4*)(vb + off);
            float4 o;
            o.x = tv.x + unpack_split(vp.x);
            o.y = tv.y + unpack_split(vp.y);
            o.z = tv.z + unpack_split(vp.z);
            o.w = tv.w + unpack_split(vp.w);
            *(float4*)(ob + off) = o;
        }
        return;
    }

    if (wid >= 8) return;   // loader warps: no output in modes 0-2

    const float* bias = (MODE == 1) ? (wsel ? bias1 : bias0) : bias0;
#pragma unroll
    for (int i = 0; i < 4; i++)
#pragma unroll
        for (int j = 0; j < 4; j++) {
            const int m = bm + warp_m * 64 + i * 16 + (lid >> 2);
            const int n = bn + warp_n * 32 + j * 8 + (lid & 3) * 2;
            const float d0 = acc[i][j][0], d1 = acc[i][j][1];
            const float d2 = acc[i][j][2], d3 = acc[i][j][3];
            if (MODE == 0) {
                float* bp = Cf + (long)b * sCf;
                *(float2*)(bp + (long)m * ldc + n)       = make_float2(d0, d1);
                *(float2*)(bp + (long)(m + 8) * ldc + n) = make_float2(d2, d3);
            } else if (MODE == 1) {
                uint32_t* dst = (wsel ? Cp2 : Cp) + (long)b * sCp;
                const float b0 = bias[n], b1 = bias[n + 1];
                *(uint2*)(dst + (long)m * ldcp + n) =
                    make_uint2(pack_split(d0 + b0), pack_split(d1 + b1));
                *(uint2*)(dst + (long)(m + 8) * ldcp + n) =
                    make_uint2(pack_split(d2 + b0), pack_split(d3 + b1));
            } else {
                uint32_t* bp = Cp + (long)b * sCp;
                const float bm0 = bias[m], bm8 = bias[m + 8];
                *(uint2*)(bp + (long)m * ldcp + n) =
                    make_uint2(pack_split(d0 + bm0), pack_split(d1 + bm0));
                *(uint2*)(bp + (long)(m + 8) * ldcp + n) =
                    make_uint2(pack_split(d2 + bm8), pack_split(d3 + bm8));
            }
        }
}

// ---------------------------------------------------------------------------
// Softmax over rows of att (fp32 in), writes packed split u32 IN PLACE.
// 192 threads, float4 vectorized: 576 float4 per row = 3 per thread.
// ---------------------------------------------------------------------------
__global__ __launch_bounds__(192)
void softmax_pack(float* __restrict__ att)
{
    const long row = blockIdx.x;
    float4* p4 = (float4*)(att + row * NPIX);
    uint4*  u4 = (uint4*)(att + row * NPIX);
    __shared__ float red[192];
    const int t = threadIdx.x;

    float4 v[3];
    float m = -INFINITY;
#pragma unroll
    for (int i = 0; i < 3; i++) {
        v[i] = p4[t + i * 192];
        m = fmaxf(m, fmaxf(fmaxf(v[i].x, v[i].y), fmaxf(v[i].z, v[i].w)));
    }
    red[t] = m; __syncthreads();
    if (t < 64) red[t] = fmaxf(red[t], fmaxf(red[t + 64], red[t + 128]));
    __syncthreads();
    for (int s = 32; s > 0; s >>= 1) {
        if (t < s) red[t] = fmaxf(red[t], red[t + s]);
        __syncthreads();
    }
    m = red[0]; __syncthreads();

    float sum = 0.f;
#pragma unroll
    for (int i = 0; i < 3; i++) {
        v[i].x = __expf(v[i].x - m); v[i].y = __expf(v[i].y - m);
        v[i].z = __expf(v[i].z - m); v[i].w = __expf(v[i].w - m);
        sum += (v[i].x + v[i].y) + (v[i].z + v[i].w);
    }
    red[t] = sum; __syncthreads();
    if (t < 64) red[t] = red[t] + red[t + 64] + red[t + 128];
    __syncthreads();
    for (int s = 32; s > 0; s >>= 1) {
        if (t < s) red[t] += red[t + s];
        __syncthreads();
    }
    const float inv = 1.f / red[0];
#pragma unroll
    for (int i = 0; i < 3; i++) {
        uint4 o;
        o.x = pack_split(v[i].x * inv);
        o.y = pack_split(v[i].y * inv);
        o.z = pack_split(v[i].z * inv);
        o.w = pack_split(v[i].w * inv);
        u4[t + i * 192] = o;
    }
}

// ---------------------------------------------------------------------------
// launch
// ---------------------------------------------------------------------------
extern "C" void kernel_launch(void* const* d_in, const int* in_sizes, int n_in,
                              void* d_out, int out_size)
{
    const float* feat = (const float*)d_in[0];
    const float* Wq   = (const float*)d_in[1];
    const float* bq   = (const float*)d_in[2];
    const float* Wk   = (const float*)d_in[3];
    const float* bk   = (const float*)d_in[4];
    const float* Wv   = (const float*)d_in[5];
    const float* bv   = (const float*)d_in[6];
    float* out = (float*)d_out;

    unsigned char* base;
    cudaGetSymbolAddress((void**)&base, g_scratch);
    uint32_t* colT = (uint32_t*)(base + OFF_COL);
    uint32_t* wqP  = (uint32_t*)(base + OFF_WQ);
    uint32_t* wkP  = (uint32_t*)(base + OFF_WK);
    uint32_t* wvP  = (uint32_t*)(base + OFF_WV);
    uint32_t* qT   = (uint32_t*)(base + OFF_QT);
    uint32_t* kT   = (uint32_t*)(base + OFF_KT);
    uint32_t* vP   = (uint32_t*)(base + OFF_VP);
    float*    att  = (float*)   (base + OFF_COL);   // alias; colT dead by then

    auto kQK  = gemm_mma<1>;
    auto kV   = gemm_mma<2>;
    auto kLOG = gemm_mma<0>;
    auto kOUT = gemm_mma<3>;
    cudaFuncSetAttribute(kQK,  cudaFuncAttributeMaxDynamicSharedMemorySize, SMEM_TOTAL);
    cudaFuncSetAttribute(kV,   cudaFuncAttributeMaxDynamicSharedMemorySize, SMEM_TOTAL);
    cudaFuncSetAttribute(kLOG, cudaFuncAttributeMaxDynamicSharedMemorySize, SMEM_TOTAL);
    cudaFuncSetAttribute(kOUT, cudaFuncAttributeMaxDynamicSharedMemorySize, SMEM_TOTAL);

    // 1) pack weights + build packed im2col
    {
        long n = (long)EMB * KDIM;
        pack_weights<<<(unsigned)((n + 255) / 256), 256>>>(Wq, Wk, Wv, wqP, wkP, wvP);
        long total = (long)BATCH * NPIX * (KDIM / 4);
        build_colT<<<(unsigned)((total + 255) / 256), 256>>>(feat, colT);
    }

    const long colS = (long)NPIX * KDIM;
    const long qtS  = (long)NPIX * EMB;
    const long attS = (long)NPIX * NPIX;

    // 2) q,k conv: D[n][e] = colT[n][:] . W[e][:] + bias[e]  (packed out)
    {
        dim3 grid(EMB / 128, NPIX / 128, 2 * BATCH);
        kQK<<<grid, 384, SMEM_TOTAL>>>(colT, colS, KDIM,
                                       wqP, 0, KDIM, wkP, KDIM,
                                       nullptr, 0, 0,
                                       qT, kT, qtS, EMB,
                                       bq, bk);
    }
    // 3) v conv: D[e][n] = Wv[e][:] . colT[n][:] + bias[e]  (packed out)
    {
        dim3 grid(NPIX / 128, EMB / 128, BATCH);
        kV<<<grid, 384, SMEM_TOTAL>>>(wvP, 0, KDIM,
                                      colT, colS, KDIM, nullptr, KDIM,
                                      nullptr, 0, 0,
                                      vP, nullptr, qtS, NPIX,
                                      bv, nullptr);
    }
    // 4) logits: att[i][j] = qT[i][:] . kT[j][:]  (K=512, fp32 out)
    {
        dim3 grid(NPIX / 128, NPIX / 128, BATCH);
        kLOG<<<grid, 384, SMEM_TOTAL>>>(qT, qtS, EMB,
                                        kT, qtS, EMB, nullptr, EMB,
                                        att, attS, NPIX,
                                        nullptr, nullptr, 0, 0,
                                        nullptr, nullptr);
    }
    // 5) softmax rows + pack u32 in place (vectorized)
    softmax_pack<<<BATCH * NPIX, 192>>>(att);

    // 6) output GEMM + fused transpose/residual:
    //    out[b][e][n] = (att[n][:] . vP[e][:]) + unpack(vP[b][e][n])
    {
        dim3 grid(EMB / 128, NPIX / 128, BATCH);
        kOUT<<<grid, 384, SMEM_TOTAL>>>((const uint32_t*)att, attS, NPIX,
                                        vP, qtS, NPIX, nullptr, NPIX,
                                        out, (long)EMB * NPIX, NPIX,
                                        vP, nullptr, qtS, NPIX,
                                        nullptr, nullptr);
    }
}

// round 15
// speedup vs baseline: 1.8099x; 1.4600x over previous
#include <cuda_runtime.h>
#include <cuda_bf16.h>
#include <math.h>
#include <stdint.h>

// ---------------------------------------------------------------------------
// Problem constants
// ---------------------------------------------------------------------------
#define BATCH 8
#define CIN   256
#define EMB   512
#define HW    48
#define NPIX  2304
#define KDIM  2304

// ---------------------------------------------------------------------------
// Scratch (packed split u32: (bf16hi<<16)|bf16lo). ~260 MB.
//   COL aliased -> fp32 att -> packed att (softmax in place)
// ---------------------------------------------------------------------------
#define COL_BYTES ((size_t)BATCH * NPIX * KDIM * 4)
#define W_BYTES   ((size_t)EMB * KDIM * 4)
#define QT_BYTES  ((size_t)BATCH * NPIX * EMB * 4)

#define OFF_COL  ((size_t)0)
#define OFF_WQ   (OFF_COL + COL_BYTES)
#define OFF_WK   (OFF_WQ + W_BYTES)
#define OFF_WV   (OFF_WK + W_BYTES)
#define OFF_QT   (OFF_WV + W_BYTES)
#define OFF_KT   (OFF_QT + QT_BYTES)
#define OFF_VP   (OFF_KT + QT_BYTES)
#define SCRATCH_BYTES (OFF_VP + QT_BYTES)

__device__ __align__(1024) unsigned char g_scratch[SCRATCH_BYTES];

// ---------------------------------------------------------------------------
// Helpers
// ---------------------------------------------------------------------------
__device__ __forceinline__ uint32_t smem_u32(const void* p) {
    uint32_t a;
    asm("{ .reg .u64 t; cvta.to.shared.u64 t, %1; cvt.u32.u64 %0, t; }"
        : "=r"(a) : "l"(p));
    return a;
}

// SW64 swizzle: 16B column bits [4:6) ^= offset bits [7:9)
#define SWZ64(o) ((o) ^ (((o) >> 3) & 0x30))

__device__ __forceinline__ uint32_t pack_split(float x) {
    __nv_bfloat16 h = __float2bfloat16(x);
    float hf = __bfloat162float(h);
    __nv_bfloat16 l = __float2bfloat16(x - hf);
    return ((uint32_t)__bfloat16_as_ushort(h) << 16) | (uint32_t)__bfloat16_as_ushort(l);
}
__device__ __forceinline__ float unpack_split(uint32_t p) {
    float hi = __bfloat162float(__ushort_as_bfloat16((unsigned short)(p >> 16)));
    float lo = __bfloat162float(__ushort_as_bfloat16((unsigned short)(p & 0xFFFF)));
    return hi + lo;
}

__device__ __forceinline__ void ldsm4(uint32_t& r0, uint32_t& r1, uint32_t& r2,
                                      uint32_t& r3, uint32_t addr) {
    asm volatile("ldmatrix.sync.aligned.m8n8.x4.shared.b16 {%0,%1,%2,%3}, [%4];"
                 : "=r"(r0), "=r"(r1), "=r"(r2), "=r"(r3) : "r"(addr));
}
__device__ __forceinline__ void mma16816(float* d, const uint32_t* a,
                                         const uint32_t* b) {
    asm volatile(
        "mma.sync.aligned.m16n8k16.row.col.f32.bf16.bf16.f32 "
        "{%0,%1,%2,%3},{%4,%5,%6,%7},{%8,%9},{%0,%1,%2,%3};"
        : "+f"(d[0]), "+f"(d[1]), "+f"(d[2]), "+f"(d[3])
        : "r"(a[0]), "r"(a[1]), "r"(a[2]), "r"(a[3]), "r"(b[0]), "r"(b[1]));
}
__device__ __forceinline__ void sts64b(uint32_t addr, uint32_t lo, uint32_t hi) {
    unsigned long long v = ((unsigned long long)hi << 32) | lo;
    asm volatile("st.shared.b64 [%0], %1;" :: "r"(addr), "l"(v) : "memory");
}

// ---------------------------------------------------------------------------
// Converters (packed u32)
// ---------------------------------------------------------------------------
__global__ void pack_weights(const float* __restrict__ Wq, const float* __restrict__ Wk,
                             const float* __restrict__ Wv,
                             uint32_t* __restrict__ oq, uint32_t* __restrict__ ok,
                             uint32_t* __restrict__ ov)
{
    long i = (long)blockIdx.x * 256 + threadIdx.x;
    const long n = (long)EMB * KDIM;
    if (i >= n) return;
    oq[i] = pack_split(Wq[i]);
    ok[i] = pack_split(Wk[i]);
    ov[i] = pack_split(Wv[i]);
}

// colT[b][n][k] packed; vectorized: each thread does 4 consecutive k.
__global__ void build_colT(const float* __restrict__ feat, uint32_t* __restrict__ colT)
{
    long idx = (long)blockIdx.x * 256 + threadIdx.x;          // quad index
    const long total = (long)BATCH * NPIX * (KDIM / 4);
    if (idx >= total) return;
    int kq = (int)(idx % (KDIM / 4));
    long t = idx / (KDIM / 4);
    int n = (int)(t % NPIX);
    int b = (int)(t / NPIX);
    int h = n / HW, w = n - HW * h;
    const float* fb = feat + (long)b * CIN * HW * HW;
    uint4 o;
    uint32_t* op = &o.x;
#pragma unroll
    for (int q = 0; q < 4; q++) {
        int k = kq * 4 + q;
        int c = k / 9, k9 = k - 9 * c;
        int ky = k9 / 3, kx = k9 - 3 * ky;
        int hs = h + ky - 1, ws = w + kx - 1;
        float v = 0.f;
        if (hs >= 0 && hs < HW && ws >= 0 && ws < HW)
            v = fb[((long)c * HW + hs) * HW + ws];
        op[q] = pack_split(v);
    }
    *(uint4*)(colT + ((long)(b * NPIX + n) * KDIM + kq * 4)) = o;
}

// ---------------------------------------------------------------------------
// GEMM: D[m][n] = sum_k A[m][k]*B[n][k], split-bf16 3-MMA, fp32 acc.
// All operands packed-split u32. LDG(uint4)->PRMT split->STS.
// 128x128 CTA, 8 warps (2x4), warp 64x32, KC=32.
// FOUR smem stages, ONE __syncthreads per PAIR of chunks (R9/R12 scheme).
// MODE: 0 fp32 out (logits) |
//       3 output GEMM: fused transpose + residual |
//       4 merged conv: z<16 -> q/k (b=z>>1, wsel=z&1; bias[col], packed out),
//                      z>=16 -> v (b=z-16; bias[row], packed out).
// Stage: [Ah 8K][Al 8K][Bh 8K][Bl 8K] = 32KB; total smem 128KB.
// ---------------------------------------------------------------------------
#define STG 32768
#define SMEM_TOTAL (4 * STG)
#define TPAD 132     // fp32 transpose tile row stride (words)
#define QTS  ((long)NPIX * EMB)

template<int MODE>
__global__ __launch_bounds__(256, 1)
void gemm_mma(const uint32_t* __restrict__ A, long sA, int lda,
              const uint32_t* __restrict__ B, long sB, int ldb,
              const uint32_t* __restrict__ Balt, const uint32_t* __restrict__ Balt2,
              int K,
              float* __restrict__ Cf, long sCf, int ldc,
              uint32_t* __restrict__ Cp, uint32_t* __restrict__ Cp2,
              uint32_t* __restrict__ Cp3,
              long sCp, int ldcp,
              const float* __restrict__ bias0, const float* __restrict__ bias1,
              const float* __restrict__ bias2)
{
    extern __shared__ __align__(128) unsigned char smem[];
    const uint32_t sbase = smem_u32(smem);
    const int tid = threadIdx.x, lid = tid & 31, wid = tid >> 5;
    const int warp_m = wid >> 2, warp_n = wid & 3;

    int b = 0, wsel = 0, bm, bn;
    bool isV = false;
    const uint32_t *Ab, *Bb;
    if (MODE == 4) {
        const int z = blockIdx.z;
        if (z < 16) {               // q/k conv: D[pixel][emb]
            b = z >> 1; wsel = z & 1;
            bm = (blockIdx.x >> 2) * 128;      // pixel tile (18)
            bn = (blockIdx.x & 3) * 128;       // emb tile (4)
            Ab = A + (long)b * sA;             // colT
            Bb = wsel ? Balt : B;              // wk / wq
        } else {                    // v conv: D[emb][pixel]
            isV = true; b = z - 16;
            bm = (blockIdx.x / 18) * 128;      // emb tile (4)
            bn = (blockIdx.x % 18) * 128;      // pixel tile (18)
            Ab = Balt2;                        // wv
            Bb = A + (long)b * sA;             // colT
        }
    } else {
        b = blockIdx.z;
        bm = blockIdx.y * 128; bn = blockIdx.x * 128;
        Ab = A + (long)b * sA;
        Bb = B + (long)b * sB;
    }

    // ---- loader mappings: uint4 segments (8 per 32-u32 row) ----
    const uint32_t* apg[4]; uint32_t ash[4];
    const uint32_t* bpg[4]; uint32_t bsh[4];
#pragma unroll
    for (int i = 0; i < 4; i++) {
        int f = tid + 256 * i; int r = f >> 3; int seg = f & 7;
        apg[i] = Ab + (long)(bm + r) * lda + seg * 4;
        bpg[i] = Bb + (long)(bn + r) * ldb + seg * 4;
        ash[i] = SWZ64((uint32_t)(r * 64 + seg * 8));
        bsh[i] = ash[i];
    }

    uint4 rga[4], rgb[4];
    auto ldg_all = [&](int c) {
#pragma unroll
        for (int i = 0; i < 4; i++) rga[i] = *(const uint4*)(apg[i] + (long)c * 32);
#pragma unroll
        for (int i = 0; i < 4; i++) rgb[i] = *(const uint4*)(bpg[i] + (long)c * 32);
    };
    auto sts_all = [&](int st) {
        const uint32_t ab = sbase + (uint32_t)st * STG;
        const uint32_t bb = ab + 16384u;
#pragma unroll
        for (int i = 0; i < 4; i++) {
            sts64b(ab + ash[i],
                   __byte_perm(rga[i].x, rga[i].y, 0x7632),
                   __byte_perm(rga[i].z, rga[i].w, 0x7632));
            sts64b(ab + 8192u + ash[i],
                   __byte_perm(rga[i].x, rga[i].y, 0x5410),
                   __byte_perm(rga[i].z, rga[i].w, 0x5410));
        }
#pragma unroll
        for (int i = 0; i < 4; i++) {
            sts64b(bb + bsh[i],
                   __byte_perm(rgb[i].x, rgb[i].y, 0x7632),
                   __byte_perm(rgb[i].z, rgb[i].w, 0x7632));
            sts64b(bb + 8192u + bsh[i],
                   __byte_perm(rgb[i].x, rgb[i].y, 0x5410),
                   __byte_perm(rgb[i].z, rgb[i].w, 0x5410));
        }
    };

    float acc[4][4][4];
#pragma unroll
    for (int i = 0; i < 4; i++)
#pragma unroll
        for (int j = 0; j < 4; j++)
#pragma unroll
            for (int r = 0; r < 4; r++) acc[i][j][r] = 0.f;

    const int sub = lid >> 3, l7 = lid & 7;
    const int arow0 = warp_m * 64 + (sub & 1) * 8 + l7;
    const int brow  = warp_n * 32 + (sub >> 1) * 8 + l7;

    auto compute = [&](int st) {
        const uint32_t stA  = sbase + (uint32_t)st * STG;
        const uint32_t stBh = stA + 16384u, stBl = stA + 24576u;
#pragma unroll
        for (int ks = 0; ks < 2; ks++) {
            uint32_t bh[4][2], bl[4][2];
            const int bkb = ks * 16 + (sub & 1) * 8;
#pragma unroll
            for (int g2 = 0; g2 < 2; g2++) {
                const uint32_t off = SWZ64((uint32_t)((brow + g2 * 16) * 64 + bkb * 2));
                ldsm4(bh[2 * g2][0], bh[2 * g2][1], bh[2 * g2 + 1][0],
                      bh[2 * g2 + 1][1], stBh + off);
                ldsm4(bl[2 * g2][0], bl[2 * g2][1], bl[2 * g2 + 1][0],
                      bl[2 * g2 + 1][1], stBl + off);
            }
            const int akb = ks * 16 + (sub >> 1) * 8;
#pragma unroll
            for (int i = 0; i < 4; i++) {
                uint32_t ah[4], al[4];
                const uint32_t off = SWZ64((uint32_t)((arow0 + i * 16) * 64 + akb * 2));
                ldsm4(ah[0], ah[1], ah[2], ah[3], stA + off);
                ldsm4(al[0], al[1], al[2], al[3], stA + 8192u + off);
#pragma unroll
                for (int j = 0; j < 4; j++) {
                    mma16816(acc[i][j], ah, bh[j]);
                    mma16816(acc[i][j], ah, bl[j]);
                    mma16816(acc[i][j], al, bh[j]);
                }
            }
        }
    };

    const int nchunk = K / 32;          // even for every call (72, 16, 72)
    const int npair  = nchunk / 2;

    // prologue: stage chunks 0 and 1
    ldg_all(0); sts_all(0);
    ldg_all(1); sts_all(1);
    __syncthreads();

    for (int p = 0; p < npair; p++) {
        const int c0 = 2 * p;
        if (c0 + 2 < nchunk) ldg_all(c0 + 2);
        compute(c0 & 3);
        if (c0 + 2 < nchunk) sts_all((c0 + 2) & 3);
        if (c0 + 3 < nchunk) ldg_all(c0 + 3);
        compute((c0 + 1) & 3);
        if (c0 + 3 < nchunk) sts_all((c0 + 3) & 3);
        __syncthreads();
    }

    // ---- epilogue ----
    if (MODE == 3) {
        // transpose via smem, then out[b][e][n_pix] = acc^T + unpack(vP)
        float* T = (float*)smem;    // pipeline smem is dead (post final sync)
#pragma unroll
        for (int i = 0; i < 4; i++)
#pragma unroll
            for (int j = 0; j < 4; j++) {
                const int ml = warp_m * 64 + i * 16 + (lid >> 2);
                const int nl = warp_n * 32 + j * 8 + (lid & 3) * 2;
                T[nl * TPAD + ml]           = acc[i][j][0];
                T[(nl + 1) * TPAD + ml]     = acc[i][j][1];
                T[nl * TPAD + ml + 8]       = acc[i][j][2];
                T[(nl + 1) * TPAD + ml + 8] = acc[i][j][3];
            }
        __syncthreads();
        float*          ob = Cf + (long)b * sCf;     // out  [E][NPIX]
        const uint32_t* vb = Cp + (long)b * sCp;     // vP   [E][NPIX]
        for (int it = tid; it < 128 * 32; it += 256) {
            const int row = it >> 5;        // emb within tile
            const int c4  = (it & 31) * 4;  // pixel within tile
            float4 tv = *(const float4*)&T[row * TPAD + c4];
            const long off = (long)(bn + row) * ldc + bm + c4;
            uint4 vp = *(const uint4*)(vb + off);
            float4 o;
            o.x = tv.x + unpack_split(vp.x);
            o.y = tv.y + unpack_split(vp.y);
            o.z = tv.z + unpack_split(vp.z);
            o.w = tv.w + unpack_split(vp.w);
            *(float4*)(ob + off) = o;
        }
        return;
    }

    if (MODE == 4) {
#pragma unroll
        for (int i = 0; i < 4; i++)
#pragma unroll
            for (int j = 0; j < 4; j++) {
                const int m = bm + warp_m * 64 + i * 16 + (lid >> 2);
                const int n = bn + warp_n * 32 + j * 8 + (lid & 3) * 2;
                const float d0 = acc[i][j][0], d1 = acc[i][j][1];
                const float d2 = acc[i][j][2], d3 = acc[i][j][3];
                if (!isV) {   // q/k: D[pixel][emb], bias over emb (cols)
                    uint32_t* dst = (wsel ? Cp2 : Cp) + (long)b * QTS;
                    const float* bias = wsel ? bias1 : bias0;
                    const float b0 = bias[n], b1 = bias[n + 1];
                    *(uint2*)(dst + (long)m * EMB + n) =
                        make_uint2(pack_split(d0 + b0), pack_split(d1 + b1));
                    *(uint2*)(dst + (long)(m + 8) * EMB + n) =
                        make_uint2(pack_split(d2 + b0), pack_split(d3 + b1));
                } else {      // v: D[emb][pixel], bias over emb (rows)
                    uint32_t* bp = Cp3 + (long)b * QTS;
                    const float bm0 = bias2[m], bm8 = bias2[m + 8];
                    *(uint2*)(bp + (long)m * NPIX + n) =
                        make_uint2(pack_split(d0 + bm0), pack_split(d1 + bm0));
                    *(uint2*)(bp + (long)(m + 8) * NPIX + n) =
                        make_uint2(pack_split(d2 + bm8), pack_split(d3 + bm8));
                }
            }
        return;
    }

    // MODE 0: fp32 out
#pragma unroll
    for (int i = 0; i < 4; i++)
#pragma unroll
        for (int j = 0; j < 4; j++) {
            const int m = bm + warp_m * 64 + i * 16 + (lid >> 2);
            const int n = bn + warp_n * 32 + j * 8 + (lid & 3) * 2;
            float* bp = Cf + (long)b * sCf;
            *(float2*)(bp + (long)m * ldc + n) =
                make_float2(acc[i][j][0], acc[i][j][1]);
            *(float2*)(bp + (long)(m + 8) * ldc + n) =
                make_float2(acc[i][j][2], acc[i][j][3]);
        }
}

// ---------------------------------------------------------------------------
// Softmax over rows of att (fp32 in), writes packed split u32 IN PLACE.
// 192 threads, float4 vectorized: 576 float4 per row = 3 per thread.
// ---------------------------------------------------------------------------
__global__ __launch_bounds__(192)
void softmax_pack(float* __restrict__ att)
{
    const long row = blockIdx.x;
    float4* p4 = (float4*)(att + row * NPIX);
    uint4*  u4 = (uint4*)(att + row * NPIX);
    __shared__ float red[192];
    const int t = threadIdx.x;

    float4 v[3];
    float m = -INFINITY;
#pragma unroll
    for (int i = 0; i < 3; i++) {
        v[i] = p4[t + i * 192];
        m = fmaxf(m, fmaxf(fmaxf(v[i].x, v[i].y), fmaxf(v[i].z, v[i].w)));
    }
    red[t] = m; __syncthreads();
    if (t < 64) red[t] = fmaxf(red[t], fmaxf(red[t + 64], red[t + 128]));
    __syncthreads();
    for (int s = 32; s > 0; s >>= 1) {
        if (t < s) red[t] = fmaxf(red[t], red[t + s]);
        __syncthreads();
    }
    m = red[0]; __syncthreads();

    float sum = 0.f;
#pragma unroll
    for (int i = 0; i < 3; i++) {
        v[i].x = __expf(v[i].x - m); v[i].y = __expf(v[i].y - m);
        v[i].z = __expf(v[i].z - m); v[i].w = __expf(v[i].w - m);
        sum += (v[i].x + v[i].y) + (v[i].z + v[i].w);
    }
    red[t] = sum; __syncthreads();
    if (t < 64) red[t] = red[t] + red[t + 64] + red[t + 128];
    __syncthreads();
    for (int s = 32; s > 0; s >>= 1) {
        if (t < s) red[t] += red[t + s];
        __syncthreads();
    }
    const float inv = 1.f / red[0];
#pragma unroll
    for (int i = 0; i < 3; i++) {
        uint4 o;
        o.x = pack_split(v[i].x * inv);
        o.y = pack_split(v[i].y * inv);
        o.z = pack_split(v[i].z * inv);
        o.w = pack_split(v[i].w * inv);
        u4[t + i * 192] = o;
    }
}

// ---------------------------------------------------------------------------
// launch
// ---------------------------------------------------------------------------
extern "C" void kernel_launch(void* const* d_in, const int* in_sizes, int n_in,
                              void* d_out, int out_size)
{
    const float* feat = (const float*)d_in[0];
    const float* Wq   = (const float*)d_in[1];
    const float* bq   = (const float*)d_in[2];
    const float* Wk   = (const float*)d_in[3];
    const float* bk   = (const float*)d_in[4];
    const float* Wv   = (const float*)d_in[5];
    const float* bv   = (const float*)d_in[6];
    float* out = (float*)d_out;

    unsigned char* base;
    cudaGetSymbolAddress((void**)&base, g_scratch);
    uint32_t* colT = (uint32_t*)(base + OFF_COL);
    uint32_t* wqP  = (uint32_t*)(base + OFF_WQ);
    uint32_t* wkP  = (uint32_t*)(base + OFF_WK);
    uint32_t* wvP  = (uint32_t*)(base + OFF_WV);
    uint32_t* qT   = (uint32_t*)(base + OFF_QT);
    uint32_t* kT   = (uint32_t*)(base + OFF_KT);
    uint32_t* vP   = (uint32_t*)(base + OFF_VP);
    float*    att  = (float*)   (base + OFF_COL);   // alias; colT dead by then

    auto kCONV = gemm_mma<4>;
    auto kLOG  = gemm_mma<0>;
    auto kOUT  = gemm_mma<3>;
    cudaFuncSetAttribute(kCONV, cudaFuncAttributeMaxDynamicSharedMemorySize, SMEM_TOTAL);
    cudaFuncSetAttribute(kLOG,  cudaFuncAttributeMaxDynamicSharedMemorySize, SMEM_TOTAL);
    cudaFuncSetAttribute(kOUT,  cudaFuncAttributeMaxDynamicSharedMemorySize, SMEM_TOTAL);

    // 1) pack weights + build packed im2col
    {
        long n = (long)EMB * KDIM;
        pack_weights<<<(unsigned)((n + 255) / 256), 256>>>(Wq, Wk, Wv, wqP, wkP, wvP);
        long total = (long)BATCH * NPIX * (KDIM / 4);
        build_colT<<<(unsigned)((total + 255) / 256), 256>>>(feat, colT);
    }

    const long colS = (long)NPIX * KDIM;
    const long attS = (long)NPIX * NPIX;

    // 2) merged conv GEMMs (q,k,v) in ONE launch: 72 x 24 CTAs
    //    z<16: q/k  D[n][e] = colT[n][:] . W[e][:] + bias[e]
    //    z>=16: v   D[e][n] = Wv[e][:] . colT[n][:] + bias[e]
    {
        dim3 grid(72, 1, 24);
        kCONV<<<grid, 256, SMEM_TOTAL>>>(colT, colS, KDIM,
                                         wqP, 0, KDIM, wkP, wvP, KDIM,
                                         nullptr, 0, 0,
                                         qT, kT, vP, QTS, 0,
                                         bq, bk, bv);
    }
    // 3) logits: att[i][j] = qT[i][:] . kT[j][:]  (K=512, fp32 out)
    {
        dim3 grid(NPIX / 128, NPIX / 128, BATCH);
        kLOG<<<grid, 256, SMEM_TOTAL>>>(qT, QTS, EMB,
                                        kT, QTS, EMB, nullptr, nullptr, EMB,
                                        att, attS, NPIX,
                                        nullptr, nullptr, nullptr, 0, 0,
                                        nullptr, nullptr, nullptr);
    }
    // 4) softmax rows + pack u32 in place (vectorized)
    softmax_pack<<<BATCH * NPIX, 192>>>(att);

    // 5) output GEMM + fused transpose/residual:
    //    out[b][e][n] = (att[n][:] . vP[e][:]) + unpack(vP[b][e][n])
    {
        dim3 grid(EMB / 128, NPIX / 128, BATCH);
        kOUT<<<grid, 256, SMEM_TOTAL>>>((const uint32_t*)att, attS, NPIX,
                                        vP, QTS, NPIX, nullptr, nullptr, NPIX,
                                        out, (long)EMB * NPIX, NPIX,
                                        vP, nullptr, nullptr, QTS, NPIX,
                                        nullptr, nullptr, nullptr);
    }
}

// round 17
// speedup vs baseline: 1.8251x; 1.0084x over previous
#include <cuda_runtime.h>
#include <cuda_bf16.h>
#include <math.h>
#include <stdint.h>

// ---------------------------------------------------------------------------
// Problem constants
// ---------------------------------------------------------------------------
#define BATCH 8
#define CIN   256
#define EMB   512
#define HW    48
#define NPIX  2304
#define KDIM  2304

// ---------------------------------------------------------------------------
// Scratch (packed split u32: (bf16hi<<16)|bf16lo). ~260 MB.
//   COL aliased -> fp32 att -> packed att (softmax in place)
// ---------------------------------------------------------------------------
#define COL_BYTES ((size_t)BATCH * NPIX * KDIM * 4)
#define W_BYTES   ((size_t)EMB * KDIM * 4)
#define QT_BYTES  ((size_t)BATCH * NPIX * EMB * 4)

#define OFF_COL  ((size_t)0)
#define OFF_WQ   (OFF_COL + COL_BYTES)
#define OFF_WK   (OFF_WQ + W_BYTES)
#define OFF_WV   (OFF_WK + W_BYTES)
#define OFF_QT   (OFF_WV + W_BYTES)
#define OFF_KT   (OFF_QT + QT_BYTES)
#define OFF_VP   (OFF_KT + QT_BYTES)
#define SCRATCH_BYTES (OFF_VP + QT_BYTES)

__device__ __align__(1024) unsigned char g_scratch[SCRATCH_BYTES];

// ---------------------------------------------------------------------------
// Helpers
// ---------------------------------------------------------------------------
__device__ __forceinline__ uint32_t smem_u32(const void* p) {
    uint32_t a;
    asm("{ .reg .u64 t; cvta.to.shared.u64 t, %1; cvt.u32.u64 %0, t; }"
        : "=r"(a) : "l"(p));
    return a;
}

// SW64 swizzle: 16B column bits [4:6) ^= offset bits [7:9)
#define SWZ64(o) ((o) ^ (((o) >> 3) & 0x30))

__device__ __forceinline__ uint32_t pack_split(float x) {
    __nv_bfloat16 h = __float2bfloat16(x);
    float hf = __bfloat162float(h);
    __nv_bfloat16 l = __float2bfloat16(x - hf);
    return ((uint32_t)__bfloat16_as_ushort(h) << 16) | (uint32_t)__bfloat16_as_ushort(l);
}
__device__ __forceinline__ float unpack_split(uint32_t p) {
    float hi = __bfloat162float(__ushort_as_bfloat16((unsigned short)(p >> 16)));
    float lo = __bfloat162float(__ushort_as_bfloat16((unsigned short)(p & 0xFFFF)));
    return hi + lo;
}

__device__ __forceinline__ void ldsm4(uint32_t& r0, uint32_t& r1, uint32_t& r2,
                                      uint32_t& r3, uint32_t addr) {
    asm volatile("ldmatrix.sync.aligned.m8n8.x4.shared.b16 {%0,%1,%2,%3}, [%4];"
                 : "=r"(r0), "=r"(r1), "=r"(r2), "=r"(r3) : "r"(addr));
}
__device__ __forceinline__ void mma16816(float* d, const uint32_t* a,
                                         const uint32_t* b) {
    asm volatile(
        "mma.sync.aligned.m16n8k16.row.col.f32.bf16.bf16.f32 "
        "{%0,%1,%2,%3},{%4,%5,%6,%7},{%8,%9},{%0,%1,%2,%3};"
        : "+f"(d[0]), "+f"(d[1]), "+f"(d[2]), "+f"(d[3])
        : "r"(a[0]), "r"(a[1]), "r"(a[2]), "r"(a[3]), "r"(b[0]), "r"(b[1]));
}
__device__ __forceinline__ void sts64b(uint32_t addr, uint32_t lo, uint32_t hi) {
    unsigned long long v = ((unsigned long long)hi << 32) | lo;
    asm volatile("st.shared.b64 [%0], %1;" :: "r"(addr), "l"(v) : "memory");
}

// ---------------------------------------------------------------------------
// Converters (packed u32)
// ---------------------------------------------------------------------------
__global__ void pack_weights(const float* __restrict__ Wq, const float* __restrict__ Wk,
                             const float* __restrict__ Wv,
                             uint32_t* __restrict__ oq, uint32_t* __restrict__ ok,
                             uint32_t* __restrict__ ov)
{
    long i = (long)blockIdx.x * 256 + threadIdx.x;
    const long n = (long)EMB * KDIM;
    if (i >= n) return;
    oq[i] = pack_split(Wq[i]);
    ok[i] = pack_split(Wk[i]);
    ov[i] = pack_split(Wv[i]);
}

// colT[b][n][k] packed; vectorized: each thread does 4 consecutive k.
__global__ void build_colT(const float* __restrict__ feat, uint32_t* __restrict__ colT)
{
    long idx = (long)blockIdx.x * 256 + threadIdx.x;          // quad index
    const long total = (long)BATCH * NPIX * (KDIM / 4);
    if (idx >= total) return;
    int kq = (int)(idx % (KDIM / 4));
    long t = idx / (KDIM / 4);
    int n = (int)(t % NPIX);
    int b = (int)(t / NPIX);
    int h = n / HW, w = n - HW * h;
    const float* fb = feat + (long)b * CIN * HW * HW;
    uint4 o;
    uint32_t* op = &o.x;
#pragma unroll
    for (int q = 0; q < 4; q++) {
        int k = kq * 4 + q;
        int c = k / 9, k9 = k - 9 * c;
        int ky = k9 / 3, kx = k9 - 3 * ky;
        int hs = h + ky - 1, ws = w + kx - 1;
        float v = 0.f;
        if (hs >= 0 && hs < HW && ws >= 0 && ws < HW)
            v = fb[((long)c * HW + hs) * HW + ws];
        op[q] = pack_split(v);
    }
    *(uint4*)(colT + ((long)(b * NPIX + n) * KDIM + kq * 4)) = o;
}

// ---------------------------------------------------------------------------
// GEMM: D[m][n] = sum_k A[m][k]*B[n][k], split-bf16 3-MMA, fp32 acc.
// All operands packed-split u32. LDG(uint4)->PRMT split->STS.
// 128x128 CTA, 8 warps (2x4), warp 64x32, KC=32.
// FOUR smem stages, ONE __syncthreads per PAIR of chunks (R9/R12 scheme).
// Prologue: chunks 0 and 1 LDG'd back-to-back (overlapped latency).
// MODE: 0 fp32 out | 1 q/k conv (bias[col], packed out, z&1 selects) |
//       2 v conv (bias[row], packed out) |
//       3 output GEMM: fused transpose + residual
// Stage: [Ah 8K][Al 8K][Bh 8K][Bl 8K] = 32KB; total smem 128KB.
// ---------------------------------------------------------------------------
#define STG 32768
#define SMEM_TOTAL (4 * STG)
#define TPAD 132     // fp32 transpose tile row stride (words)

template<int MODE>
__global__ __launch_bounds__(256, 1)
void gemm_mma(const uint32_t* __restrict__ A, long sA, int lda,
              const uint32_t* __restrict__ B, long sB, int ldb,
              const uint32_t* __restrict__ Balt,
              int K,
              float* __restrict__ Cf, long sCf, int ldc,
              uint32_t* __restrict__ Cp, uint32_t* __restrict__ Cp2,
              long sCp, int ldcp,
              const float* __restrict__ bias0, const float* __restrict__ bias1)
{
    extern __shared__ __align__(128) unsigned char smem[];
    const uint32_t sbase = smem_u32(smem);
    const int tid = threadIdx.x, lid = tid & 31, wid = tid >> 5;
    const int warp_m = wid >> 2, warp_n = wid & 3;

    int bz = blockIdx.z, b, wsel = 0;
    if (MODE == 1) { b = bz >> 1; wsel = bz & 1; } else { b = bz; }
    const int bm = blockIdx.y * 128, bn = blockIdx.x * 128;

    const uint32_t* Ab = A + (long)b * sA;
    const uint32_t* Bb = (MODE == 1) ? (wsel ? Balt : B) : (B + (long)b * sB);

    // ---- loader mappings: uint4 segments (8 per 32-u32 row) ----
    const uint32_t* apg[4]; uint32_t ash[4];
    const uint32_t* bpg[4]; uint32_t bsh[4];
#pragma unroll
    for (int i = 0; i < 4; i++) {
        int f = tid + 256 * i; int r = f >> 3; int seg = f & 7;
        apg[i] = Ab + (long)(bm + r) * lda + seg * 4;
        bpg[i] = Bb + (long)(bn + r) * ldb + seg * 4;
        ash[i] = SWZ64((uint32_t)(r * 64 + seg * 8));
        bsh[i] = ash[i];
    }

    uint4 rga[4], rgb[4];
    auto ldg_all = [&](int c) {
#pragma unroll
        for (int i = 0; i < 4; i++) rga[i] = *(const uint4*)(apg[i] + (long)c * 32);
#pragma unroll
        for (int i = 0; i < 4; i++) rgb[i] = *(const uint4*)(bpg[i] + (long)c * 32);
    };
    auto sts_all = [&](int st) {
        const uint32_t ab = sbase + (uint32_t)st * STG;
        const uint32_t bb = ab + 16384u;
#pragma unroll
        for (int i = 0; i < 4; i++) {
            sts64b(ab + ash[i],
                   __byte_perm(rga[i].x, rga[i].y, 0x7632),
                   __byte_perm(rga[i].z, rga[i].w, 0x7632));
            sts64b(ab + 8192u + ash[i],
                   __byte_perm(rga[i].x, rga[i].y, 0x5410),
                   __byte_perm(rga[i].z, rga[i].w, 0x5410));
        }
#pragma unroll
        for (int i = 0; i < 4; i++) {
            sts64b(bb + bsh[i],
                   __byte_perm(rgb[i].x, rgb[i].y, 0x7632),
                   __byte_perm(rgb[i].z, rgb[i].w, 0x7632));
            sts64b(bb + 8192u + bsh[i],
                   __byte_perm(rgb[i].x, rgb[i].y, 0x5410),
                   __byte_perm(rgb[i].z, rgb[i].w, 0x5410));
        }
    };

    float acc[4][4][4];
#pragma unroll
    for (int i = 0; i < 4; i++)
#pragma unroll
        for (int j = 0; j < 4; j++)
#pragma unroll
            for (int r = 0; r < 4; r++) acc[i][j][r] = 0.f;

    const int sub = lid >> 3, l7 = lid & 7;
    const int arow0 = warp_m * 64 + (sub & 1) * 8 + l7;
    const int brow  = warp_n * 32 + (sub >> 1) * 8 + l7;

    auto compute = [&](int st) {
        const uint32_t stA  = sbase + (uint32_t)st * STG;
        const uint32_t stBh = stA + 16384u, stBl = stA + 24576u;
#pragma unroll
        for (int ks = 0; ks < 2; ks++) {
            uint32_t bh[4][2], bl[4][2];
            const int bkb = ks * 16 + (sub & 1) * 8;
#pragma unroll
            for (int g2 = 0; g2 < 2; g2++) {
                const uint32_t off = SWZ64((uint32_t)((brow + g2 * 16) * 64 + bkb * 2));
                ldsm4(bh[2 * g2][0], bh[2 * g2][1], bh[2 * g2 + 1][0],
                      bh[2 * g2 + 1][1], stBh + off);
                ldsm4(bl[2 * g2][0], bl[2 * g2][1], bl[2 * g2 + 1][0],
                      bl[2 * g2 + 1][1], stBl + off);
            }
            const int akb = ks * 16 + (sub >> 1) * 8;
#pragma unroll
            for (int i = 0; i < 4; i++) {
                uint32_t ah[4], al[4];
                const uint32_t off = SWZ64((uint32_t)((arow0 + i * 16) * 64 + akb * 2));
                ldsm4(ah[0], ah[1], ah[2], ah[3], stA + off);
                ldsm4(al[0], al[1], al[2], al[3], stA + 8192u + off);
#pragma unroll
                for (int j = 0; j < 4; j++) {
                    mma16816(acc[i][j], ah, bh[j]);
                    mma16816(acc[i][j], ah, bl[j]);
                    mma16816(acc[i][j], al, bh[j]);
                }
            }
        }
    };

    const int nchunk = K / 32;          // always even here (72, 16, 72)
    const int npair  = nchunk / 2;

    // prologue: chunks 0 and 1 loaded back-to-back (overlapped latency),
    // chunk 1 held in a second register set until chunk 0 is stored.
    {
        uint4 rga1[4], rgb1[4];
        ldg_all(0);
#pragma unroll
        for (int i = 0; i < 4; i++) rga1[i] = *(const uint4*)(apg[i] + 32);
#pragma unroll
        for (int i = 0; i < 4; i++) rgb1[i] = *(const uint4*)(bpg[i] + 32);
        sts_all(0);
#pragma unroll
        for (int i = 0; i < 4; i++) rga[i] = rga1[i];
#pragma unroll
        for (int i = 0; i < 4; i++) rgb[i] = rgb1[i];
        sts_all(1);
    }
    __syncthreads();

    for (int p = 0; p < npair; p++) {
        const int c0 = 2 * p;
        if (c0 + 2 < nchunk) ldg_all(c0 + 2);
        compute(c0 & 3);
        if (c0 + 2 < nchunk) sts_all((c0 + 2) & 3);
        if (c0 + 3 < nchunk) ldg_all(c0 + 3);
        compute((c0 + 1) & 3);
        if (c0 + 3 < nchunk) sts_all((c0 + 3) & 3);
        __syncthreads();
    }

    // ---- epilogue ----
    if (MODE == 3) {
        // transpose via smem, then out[b][e][n_pix] = acc^T + unpack(vP)
        float* T = (float*)smem;    // pipeline smem is dead (post final sync)
#pragma unroll
        for (int i = 0; i < 4; i++)
#pragma unroll
            for (int j = 0; j < 4; j++) {
                const int ml = warp_m * 64 + i * 16 + (lid >> 2);
                const int nl = warp_n * 32 + j * 8 + (lid & 3) * 2;
                T[nl * TPAD + ml]           = acc[i][j][0];
                T[(nl + 1) * TPAD + ml]     = acc[i][j][1];
                T[nl * TPAD + ml + 8]       = acc[i][j][2];
                T[(nl + 1) * TPAD + ml + 8] = acc[i][j][3];
            }
        __syncthreads();
        float*          ob = Cf + (long)b * sCf;     // out  [E][NPIX]
        const uint32_t* vb = Cp + (long)b * sCp;     // vP   [E][NPIX]
        for (int it = tid; it < 128 * 32; it += 256) {
            const int row = it >> 5;        // emb within tile
            const int c4  = (it & 31) * 4;  // pixel within tile
            float4 tv = *(const float4*)&T[row * TPAD + c4];
            const long off = (long)(bn + row) * ldc + bm + c4;
            uint4 vp = *(const uint4*)(vb + off);
            float4 o;
            o.x = tv.x + unpack_split(vp.x);
            o.y = tv.y + unpack_split(vp.y);
            o.z = tv.z + unpack_split(vp.z);
            o.w = tv.w + unpack_split(vp.w);
            *(float4*)(ob + off) = o;
        }
        return;
    }

    const float* bias = (MODE == 1) ? (wsel ? bias1 : bias0) : bias0;
#pragma unroll
    for (int i = 0; i < 4; i++)
#pragma unroll
        for (int j = 0; j < 4; j++) {
            const int m = bm + warp_m * 64 + i * 16 + (lid >> 2);
            const int n = bn + warp_n * 32 + j * 8 + (lid & 3) * 2;
            const float d0 = acc[i][j][0], d1 = acc[i][j][1];
            const float d2 = acc[i][j][2], d3 = acc[i][j][3];
            if (MODE == 0) {
                float* bp = Cf + (long)b * sCf;
                *(float2*)(bp + (long)m * ldc + n)       = make_float2(d0, d1);
                *(float2*)(bp + (long)(m + 8) * ldc + n) = make_float2(d2, d3);
            } else if (MODE == 1) {
                uint32_t* dst = (wsel ? Cp2 : Cp) + (long)b * sCp;
                const float b0 = bias[n], b1 = bias[n + 1];
                *(uint2*)(dst + (long)m * ldcp + n) =
                    make_uint2(pack_split(d0 + b0), pack_split(d1 + b1));
                *(uint2*)(dst + (long)(m + 8) * ldcp + n) =
                    make_uint2(pack_split(d2 + b0), pack_split(d3 + b1));
            } else {
                uint32_t* bp = Cp + (long)b * sCp;
                const float bm0 = bias[m], bm8 = bias[m + 8];
                *(uint2*)(bp + (long)m * ldcp + n) =
                    make_uint2(pack_split(d0 + bm0), pack_split(d1 + bm0));
                *(uint2*)(bp + (long)(m + 8) * ldcp + n) =
                    make_uint2(pack_split(d2 + bm8), pack_split(d3 + bm8));
            }
        }
}

// ---------------------------------------------------------------------------
// Softmax over rows of att (fp32 in), writes packed split u32 IN PLACE.
// 192 threads, float4 vectorized: 576 float4 per row = 3 per thread.
// ---------------------------------------------------------------------------
__global__ __launch_bounds__(192)
void softmax_pack(float* __restrict__ att)
{
    const long row = blockIdx.x;
    float4* p4 = (float4*)(att + row * NPIX);
    uint4*  u4 = (uint4*)(att + row * NPIX);
    __shared__ float red[192];
    const int t = threadIdx.x;

    float4 v[3];
    float m = -INFINITY;
#pragma unroll
    for (int i = 0; i < 3; i++) {
        v[i] = p4[t + i * 192];
        m = fmaxf(m, fmaxf(fmaxf(v[i].x, v[i].y), fmaxf(v[i].z, v[i].w)));
    }
    red[t] = m; __syncthreads();
    if (t < 64) red[t] = fmaxf(red[t], fmaxf(red[t + 64], red[t + 128]));
    __syncthreads();
    for (int s = 32; s > 0; s >>= 1) {
        if (t < s) red[t] = fmaxf(red[t], red[t + s]);
        __syncthreads();
    }
    m = red[0]; __syncthreads();

    float sum = 0.f;
#pragma unroll
    for (int i = 0; i < 3; i++) {
        v[i].x = __expf(v[i].x - m); v[i].y = __expf(v[i].y - m);
        v[i].z = __expf(v[i].z - m); v[i].w = __expf(v[i].w - m);
        sum += (v[i].x + v[i].y) + (v[i].z + v[i].w);
    }
    red[t] = sum; __syncthreads();
    if (t < 64) red[t] = red[t] + red[t + 64] + red[t + 128];
    __syncthreads();
    for (int s = 32; s > 0; s >>= 1) {
        if (t < s) red[t] += red[t + s];
        __syncthreads();
    }
    const float inv = 1.f / red[0];
#pragma unroll
    for (int i = 0; i < 3; i++) {
        uint4 o;
        o.x = pack_split(v[i].x * inv);
        o.y = pack_split(v[i].y * inv);
        o.z = pack_split(v[i].z * inv);
        o.w = pack_split(v[i].w * inv);
        u4[t + i * 192] = o;
    }
}

// ---------------------------------------------------------------------------
// launch
// ---------------------------------------------------------------------------
extern "C" void kernel_launch(void* const* d_in, const int* in_sizes, int n_in,
                              void* d_out, int out_size)
{
    const float* feat = (const float*)d_in[0];
    const float* Wq   = (const float*)d_in[1];
    const float* bq   = (const float*)d_in[2];
    const float* Wk   = (const float*)d_in[3];
    const float* bk   = (const float*)d_in[4];
    const float* Wv   = (const float*)d_in[5];
    const float* bv   = (const float*)d_in[6];
    float* out = (float*)d_out;

    unsigned char* base;
    cudaGetSymbolAddress((void**)&base, g_scratch);
    uint32_t* colT = (uint32_t*)(base + OFF_COL);
    uint32_t* wqP  = (uint32_t*)(base + OFF_WQ);
    uint32_t* wkP  = (uint32_t*)(base + OFF_WK);
    uint32_t* wvP  = (uint32_t*)(base + OFF_WV);
    uint32_t* qT   = (uint32_t*)(base + OFF_QT);
    uint32_t* kT   = (uint32_t*)(base + OFF_KT);
    uint32_t* vP   = (uint32_t*)(base + OFF_VP);
    float*    att  = (float*)   (base + OFF_COL);   // alias; colT dead by then

    auto kQK  = gemm_mma<1>;
    auto kV   = gemm_mma<2>;
    auto kLOG = gemm_mma<0>;
    auto kOUT = gemm_mma<3>;
    cudaFuncSetAttribute(kQK,  cudaFuncAttributeMaxDynamicSharedMemorySize, SMEM_TOTAL);
    cudaFuncSetAttribute(kV,   cudaFuncAttributeMaxDynamicSharedMemorySize, SMEM_TOTAL);
    cudaFuncSetAttribute(kLOG, cudaFuncAttributeMaxDynamicSharedMemorySize, SMEM_TOTAL);
    cudaFuncSetAttribute(kOUT, cudaFuncAttributeMaxDynamicSharedMemorySize, SMEM_TOTAL);

    // 1) pack weights + build packed im2col
    {
        long n = (long)EMB * KDIM;
        pack_weights<<<(unsigned)((n + 255) / 256), 256>>>(Wq, Wk, Wv, wqP, wkP, wvP);
        long total = (long)BATCH * NPIX * (KDIM / 4);
        build_colT<<<(unsigned)((total + 255) / 256), 256>>>(feat, colT);
    }

    const long colS = (long)NPIX * KDIM;
    const long qtS  = (long)NPIX * EMB;
    const long attS = (long)NPIX * NPIX;

    // 2) q,k conv: D[n][e] = colT[n][:] . W[e][:] + bias[e]  (packed out)
    {
        dim3 grid(EMB / 128, NPIX / 128, 2 * BATCH);
        kQK<<<grid, 256, SMEM_TOTAL>>>(colT, colS, KDIM,
                                       wqP, 0, KDIM, wkP, KDIM,
                                       nullptr, 0, 0,
                                       qT, kT, qtS, EMB,
                                       bq, bk);
    }
    // 3) v conv: D[e][n] = Wv[e][:] . colT[n][:] + bias[e]  (packed out)
    {
        dim3 grid(NPIX / 128, EMB / 128, BATCH);
        kV<<<grid, 256, SMEM_TOTAL>>>(wvP, 0, KDIM,
                                      colT, colS, KDIM, nullptr, KDIM,
                                      nullptr, 0, 0,
                                      vP, nullptr, qtS, NPIX,
                                      bv, nullptr);
    }
    // 4) logits: att[i][j] = qT[i][:] . kT[j][:]  (K=512, fp32 out)
    {
        dim3 grid(NPIX / 128, NPIX / 128, BATCH);
        kLOG<<<grid, 256, SMEM_TOTAL>>>(qT, qtS, EMB,
                                        kT, qtS, EMB, nullptr, EMB,
                                        att, attS, NPIX,
                                        nullptr, nullptr, 0, 0,
                                        nullptr, nullptr);
    }
    // 5) softmax rows + pack u32 in place (vectorized)
    softmax_pack<<<BATCH * NPIX, 192>>>(att);

    // 6) output GEMM + fused transpose/residual:
    //    out[b][e][n] = (att[n][:] . vP[e][:]) + unpack(vP[b][e][n])
    {
        dim3 grid(EMB / 128, NPIX / 128, BATCH);
        kOUT<<<grid, 256, SMEM_TOTAL>>>((const uint32_t*)att, attS, NPIX,
                                        vP, qtS, NPIX, nullptr, NPIX,
                                        out, (long)EMB * NPIX, NPIX,
                                        vP, nullptr, qtS, NPIX,
                                        nullptr, nullptr);
    }
}